// round 16
// baseline (speedup 1.0000x reference)
#include <cuda_runtime.h>
#include <cuda_bf16.h>
#include <cstdint>

#define Vn 30000
#define Kn 17
#define En 128
#define Hn 128
#define Bn 128
#define Tn 512
#define G4H 512   // 4*H

// ---------------- scratch (device globals; allocation-free) ----------------
// xp stored bf16, layout [dir][t][rank][b][128] with gate-permuted last dim:
//   c = (wid'<<4) | ((gate&2)<<2) | (a<<1) | (gate&1),  j = 32*rank + 4*wid' + a
__device__ __nv_bfloat16 g_xp_bf[(size_t)2 * Tn * 4 * Bn * 128];
__device__ __nv_bfloat16 g_hs_bf[(size_t)Tn * Bn * 2 * Hn];   // [t*B+b][256]
__device__ float g_em[(size_t)Bn * Tn * Kn];                  // [b][t][k]
__device__ float g_llh[Bn];
__device__ __nv_bfloat16 g_wih_bf[2 * (size_t)G4H * En];      // [dir][g][k]
__device__ __nv_bfloat16 g_wemit_bf[32 * 256];                // rows>=17 zero
__device__ float g_bias[2 * G4H];

__device__ __forceinline__ float tanha(float x) {
    float r; asm("tanh.approx.f32 %0,%1;" : "=f"(r) : "f"(x)); return r;
}
__device__ __forceinline__ float siga(float x) {
    return 0.5f * tanha(0.5f * x) + 0.5f;
}

// ================= Kernel 0: weight conversions only (embed stays fp32) =====
__global__ __launch_bounds__(256) void k_cvt(
    const float* __restrict__ wf, const float* __restrict__ wb,
    const float* __restrict__ bihf, const float* __restrict__ bhhf,
    const float* __restrict__ bihb, const float* __restrict__ bhhb,
    const float* __restrict__ w_emit)
{
    int i = blockIdx.x * 256 + threadIdx.x;
    if (i < G4H * En / 2) {
        float2 v = ((const float2*)wf)[i];
        ((__nv_bfloat162*)g_wih_bf)[i] = __floats2bfloat162_rn(v.x, v.y);
        float2 u = ((const float2*)wb)[i];
        ((__nv_bfloat162*)g_wih_bf)[G4H * En / 2 + i] = __floats2bfloat162_rn(u.x, u.y);
    }
    if (i < G4H) {
        g_bias[i] = bihf[i] + bhhf[i];
        g_bias[G4H + i] = bihb[i] + bhhb[i];
    }
    if (i < 32 * 128) {   // w_emit padded to 32 rows, bf16
        int row = i >> 7, col2 = i & 127;
        __nv_bfloat162 v;
        if (row < Kn) {
            v = __floats2bfloat162_rn(w_emit[row * 256 + 2 * col2],
                                      w_emit[row * 256 + 2 * col2 + 1]);
        } else {
            v = __floats2bfloat162_rn(0.0f, 0.0f);
        }
        ((__nv_bfloat162*)g_wemit_bf)[i] = v;
    }
}

// ---------------- mma / cluster helpers ----------------
__device__ __forceinline__ uint32_t smaddr(const void* p) {
    return (uint32_t)__cvta_generic_to_shared(p);
}
__device__ __forceinline__ void ldm4(uint32_t& r0, uint32_t& r1, uint32_t& r2, uint32_t& r3, uint32_t a) {
    asm volatile("ldmatrix.sync.aligned.m8n8.x4.shared.b16 {%0,%1,%2,%3},[%4];"
                 : "=r"(r0), "=r"(r1), "=r"(r2), "=r"(r3) : "r"(a));
}
__device__ __forceinline__ void mma16816(float* c, uint32_t a0, uint32_t a1, uint32_t a2, uint32_t a3,
                                         uint32_t b0, uint32_t b1) {
    asm volatile("mma.sync.aligned.m16n8k16.row.col.f32.bf16.bf16.f32 "
                 "{%0,%1,%2,%3},{%4,%5,%6,%7},{%8,%9},{%0,%1,%2,%3};"
                 : "+f"(c[0]), "+f"(c[1]), "+f"(c[2]), "+f"(c[3])
                 : "r"(a0), "r"(a1), "r"(a2), "r"(a3), "r"(b0), "r"(b1));
}
__device__ __forceinline__ uint32_t mapa_u32(uint32_t a, uint32_t rnk) {
    uint32_t d; asm("mapa.shared::cluster.u32 %0,%1,%2;" : "=r"(d) : "r"(a), "r"(rnk));
    return d;
}
__device__ __forceinline__ void mbar_init(uint32_t bar, uint32_t cnt) {
    asm volatile("mbarrier.init.shared.b64 [%0],%1;" :: "r"(bar), "r"(cnt) : "memory");
}
__device__ __forceinline__ void mbar_expect(uint32_t bar, uint32_t tx) {
    asm volatile("mbarrier.arrive.expect_tx.shared.b64 _,[%0],%1;" :: "r"(bar), "r"(tx) : "memory");
}
__device__ __forceinline__ void mbar_wait_cluster(uint32_t bar, uint32_t parity) {
    uint32_t done;
    do {
        asm volatile("{\n\t.reg .pred p;\n\t"
                     "mbarrier.try_wait.parity.acquire.cluster.shared::cta.b64 p,[%1],%2,0x989680;\n\t"
                     "selp.b32 %0,1,0,p;\n\t}"
                     : "=r"(done) : "r"(bar), "r"(parity) : "memory");
    } while (!done);
}
__device__ __forceinline__ void st_async_b64(uint32_t raddr, unsigned long long v, uint32_t rbar) {
    asm volatile("st.async.shared::cluster.mbarrier::complete_tx::bytes.b64 [%0],%1,[%2];"
                 :: "r"(raddr), "l"(v), "r"(rbar) : "memory");
}

#define ASTR 136   // bf16 elems per smem row (128 + 8 pad: conflict-free ldmatrix)

// ================= Kernel 1: input projection (tensor cores, permuted out) ==
// grid (8, 512): x = nt (dir*4+gate), y = t. A gathered from fp32 embed
// with inline bf16 conversion (table stays fp32, L2-resident).
__global__ __launch_bounds__(256) void k_xp2(const int* __restrict__ ids,
                                             const float* __restrict__ embed)
{
    extern __shared__ char sm[];
    __nv_bfloat16* As = (__nv_bfloat16*)sm;                      // [128][136]
    __nv_bfloat16* Bs = (__nv_bfloat16*)(sm + 128 * ASTR * 2);   // [128][136]
    float* sbias = (float*)(sm + 2 * 128 * ASTR * 2);            // [128]

    const int t = blockIdx.y;
    const int nt = blockIdx.x;         // 0..7
    const int dir = nt >> 2;
    const int gate = nt & 3;
    const int gBase = gate * 128;
    const int tid = threadIdx.x;

    {
        int r = tid >> 1, half = tid & 1;
        int id = ids[r * Tn + t];
        const float4* src = (const float4*)(embed + (size_t)id * En + half * 64);
        __nv_bfloat162* dst = (__nv_bfloat162*)(As + r * ASTR + half * 64);
#pragma unroll
        for (int i = 0; i < 16; i++) {
            float4 v = src[i];
            dst[2 * i]     = __floats2bfloat162_rn(v.x, v.y);
            dst[2 * i + 1] = __floats2bfloat162_rn(v.z, v.w);
        }
        const uint4* wsrc = (const uint4*)(g_wih_bf + ((size_t)dir * G4H + gBase + r) * En + half * 64);
        uint4* wdst = (uint4*)(Bs + r * ASTR + half * 64);
#pragma unroll
        for (int i = 0; i < 8; i++) wdst[i] = wsrc[i];
    }
    if (tid < 128) sbias[tid] = g_bias[dir * G4H + gBase + tid];
    __syncthreads();

    const int wid = tid >> 5, lane = tid & 31;
    const int wm = (wid & 3) * 32;
    const int wn = (wid >> 2) * 64;

    float acc[2][8][4];
#pragma unroll
    for (int im = 0; im < 2; im++)
#pragma unroll
        for (int inn = 0; inn < 8; inn++)
#pragma unroll
            for (int r = 0; r < 4; r++) acc[im][inn][r] = 0.0f;

    const int lr = lane & 15, lc = lane >> 4;
#pragma unroll
    for (int kk = 0; kk < 8; kk++) {
        uint32_t a[2][4];
#pragma unroll
        for (int im = 0; im < 2; im++) {
            uint32_t ad = smaddr(As + (wm + im * 16 + lr) * ASTR + kk * 16 + lc * 8);
            ldm4(a[im][0], a[im][1], a[im][2], a[im][3], ad);
        }
        uint32_t b[4][4];
#pragma unroll
        for (int np = 0; np < 4; np++) {
            uint32_t ad = smaddr(Bs + (wn + np * 16 + lr) * ASTR + kk * 16 + lc * 8);
            ldm4(b[np][0], b[np][1], b[np][2], b[np][3], ad);
        }
#pragma unroll
        for (int im = 0; im < 2; im++)
#pragma unroll
            for (int inn = 0; inn < 8; inn++) {
                int np = inn >> 1, hf = inn & 1;
                uint32_t bb0 = hf ? b[np][1] : b[np][0];
                uint32_t bb1 = hf ? b[np][3] : b[np][2];
                mma16816(acc[im][inn], a[im][0], a[im][1], a[im][2], a[im][3], bb0, bb1);
            }
    }

    // epilogue: bias, bf16, permuted scatter to [dir][trow][rank][b][c]
    const int trow = dir ? (Tn - 1 - t) : t;
#pragma unroll
    for (int im = 0; im < 2; im++)
#pragma unroll
        for (int inn = 0; inn < 8; inn++) {
            int gl = wn + inn * 8 + 2 * (lane & 3);       // j (even)
            float bx = sbias[gl], by = sbias[gl + 1];
            int rho = gl >> 5, jl = gl & 31;
            int widp = jl >> 2, aa = jl & 3;
            int cpos = (widp << 4) | ((gate & 2) << 2) | (aa << 1) | (gate & 1);
            int row0 = wm + im * 16 + (lane >> 2);
            size_t base = (((size_t)(dir * Tn + trow) * 4 + rho) * Bn) * 128;
            g_xp_bf[base + (size_t)row0 * 128 + cpos]     = __float2bfloat16(acc[im][inn][0] + bx);
            g_xp_bf[base + (size_t)row0 * 128 + cpos + 2] = __float2bfloat16(acc[im][inn][1] + by);
            g_xp_bf[base + (size_t)(row0 + 8) * 128 + cpos]     = __float2bfloat16(acc[im][inn][2] + bx);
            g_xp_bf[base + (size_t)(row0 + 8) * 128 + cpos + 2] = __float2bfloat16(acc[im][inn][3] + by);
        }
}

// ================= Kernel 2: cluster-4 j-split BiLSTM recurrence ============
// R13 protocol (monolithic wait, two alternating mbarriers); Sg staging
// removed — senders read the own-slice values directly from Hsm[nb] (the
// epilogue's ownH stores put them at exactly the needed offsets).
__global__ __launch_bounds__(256, 1) __cluster_dims__(4, 1, 1)
void k_lstm6(const float* __restrict__ whhf, const float* __restrict__ whhb)
{
    __shared__ __nv_bfloat16 Wsm[128 * ASTR];
    __shared__ __nv_bfloat16 Hsm[2][16 * ASTR];
    __shared__ __align__(8) unsigned long long hbar_s[2];

    const int cid = blockIdx.x >> 2;
    const int rank = blockIdx.x & 3;
    const int dir = cid >> 3;
    const int b0 = (cid & 7) * 16;
    const float* whh = dir ? whhb : whhf;
    const int tid = threadIdx.x;
    const int wid = tid >> 5, lane = tid & 31;

    // ---- load my 128 permuted W_hh rows as bf16 ----
    {
        int c = tid >> 1, half = tid & 1;
        int gate = (c & 1) + 2 * ((c >> 3) & 1);
        int jl = 4 * (c >> 4) + ((c & 7) >> 1);
        int grow = gate * 128 + 32 * rank + jl;
        const float2* src = (const float2*)(whh + (size_t)grow * Hn + half * 64);
        __nv_bfloat162* dst = (__nv_bfloat162*)(Wsm + c * ASTR + half * 64);
#pragma unroll
        for (int i = 0; i < 32; i++) {
            float2 v = src[i];
            dst[i] = __floats2bfloat162_rn(v.x, v.y);
        }
    }
    for (int i = tid; i < 2 * 16 * ASTR / 2; i += 256) ((uint32_t*)Hsm)[i] = 0u;

    const uint32_t hbar0 = smaddr(&hbar_s[0]);
    const uint32_t hbar1 = smaddr(&hbar_s[1]);
    if (tid == 0) {
        mbar_init(hbar0, 1);
        mbar_init(hbar1, 1);
        mbar_expect(hbar0, 3072);   // phase 0 of barrier 0 (3 peers x 1KB)
        mbar_expect(hbar1, 3072);   // phase 0 of barrier 1
    }
    __syncthreads();
    asm volatile("barrier.cluster.arrive.aligned;" ::: "memory");
    asm volatile("barrier.cluster.wait.aligned;" ::: "memory");

    // ---- hoist W fragments (step-invariant) ----
    const int lr = lane & 15, lc = lane >> 4;
    uint32_t bw[8][4];
#pragma unroll
    for (int kk = 0; kk < 8; kk++)
        ldm4(bw[kk][0], bw[kk][1], bw[kk][2], bw[kk][3],
             smaddr(Wsm + (16 * wid + lr) * ASTR + kk * 16 + lc * 8));

    // ---- thread coords & precomputed addresses ----
    const int a = lane & 3, r = lane >> 2;
    const int cb = 16 * wid + 2 * a;
    const int j = 32 * rank + 4 * wid + a;
    const int destrow = (a & 1) ? (r + 8) : r;
    const int destcol = (a & 1) ? (j - 1) : j;   // even
    uint32_t* ownH[2];
    ownH[0] = (uint32_t*)&Hsm[0][destrow * ASTR + destcol];
    ownH[1] = (uint32_t*)&Hsm[1][destrow * ASTR + destcol];

    // sender thread (tid<128): reads own-slice u64 from Hsm[nb], sends to 3 peers
    const int srow = tid >> 3, spr = tid & 7;
    const unsigned long long* sndSrc[2];
    sndSrc[0] = (const unsigned long long*)(Hsm[0] + srow * ASTR + 32 * rank + 4 * spr);
    sndSrc[1] = (const unsigned long long*)(Hsm[1] + srow * ASTR + 32 * rank + 4 * spr);
    uint32_t aR[2][4], barH[2][4];
#pragma unroll
    for (int buf = 0; buf < 2; buf++) {
        uint32_t la = smaddr(Hsm[buf] + srow * ASTR + 32 * rank + 4 * spr);
#pragma unroll
        for (int p = 0; p < 4; p++) aR[buf][p] = mapa_u32(la, p);
    }
#pragma unroll
    for (int p = 0; p < 4; p++) {
        barH[0][p] = mapa_u32(hbar0, p);
        barH[1][p] = mapa_u32(hbar1, p);
    }

    const uint32_t* xb = (const uint32_t*)g_xp_bf
        + ((size_t)dir * Tn * 4 + rank) * Bn * 64 + (size_t)(b0 + r) * 64 + (cb >> 1);
    const size_t tstep = 4 * (size_t)Bn * 64;   // u32 per t

    const uint32_t ghs_ofs = (uint32_t)(((b0 + destrow) * 256 + dir * 128 + destcol) >> 1);
    uint32_t* ghs = (uint32_t*)g_hs_bf;

    uint32_t v00 = xb[0], v01 = xb[4], v10 = xb[512], v11 = xb[516];
    float creg0 = 0.0f, creg1 = 0.0f;

    for (int t = 0; t < Tn; t++) {
        uint32_t n00, n01, n10, n11;
        if (t + 1 < Tn) {
            const uint32_t* p = xb + (size_t)(t + 1) * tstep;
            n00 = p[0]; n01 = p[4]; n10 = p[512]; n11 = p[516];
        }
        // acc init from permuted xp: acc0={i,f}(r),(r+8); acc1={g,o}(r),(r+8)
        float acc0[4], acc1[4];
        {
            __nv_bfloat162 u;
            u = *(__nv_bfloat162*)&v00; acc0[0] = __bfloat162float(u.x); acc0[1] = __bfloat162float(u.y);
            u = *(__nv_bfloat162*)&v10; acc0[2] = __bfloat162float(u.x); acc0[3] = __bfloat162float(u.y);
            u = *(__nv_bfloat162*)&v01; acc1[0] = __bfloat162float(u.x); acc1[1] = __bfloat162float(u.y);
            u = *(__nv_bfloat162*)&v11; acc1[2] = __bfloat162float(u.x); acc1[3] = __bfloat162float(u.y);
        }
        // GEMM from current h buffer
        const __nv_bfloat16* hb = Hsm[t & 1];
#pragma unroll
        for (int kk = 0; kk < 8; kk++) {
            uint32_t a0, a1, a2, a3;
            ldm4(a0, a1, a2, a3, smaddr(hb + lr * ASTR + kk * 16 + lc * 8));
            mma16816(acc0, a0, a1, a2, a3, bw[kk][0], bw[kk][2]);
            mma16816(acc1, a0, a1, a2, a3, bw[kk][1], bw[kk][3]);
        }
        // pointwise in registers: (i,f,g,o) at (b=r / r+8, j)
        creg0 = siga(acc0[1]) * creg0 + siga(acc0[0]) * tanha(acc1[0]);
        float h0 = siga(acc1[1]) * tanha(creg0);
        creg1 = siga(acc0[3]) * creg1 + siga(acc0[2]) * tanha(acc1[2]);
        float h1 = siga(acc1[3]) * tanha(creg1);

        float h0p = __shfl_xor_sync(0xffffffffu, h0, 1);
        float h1p = __shfl_xor_sync(0xffffffffu, h1, 1);
        __nv_bfloat162 pk = (a & 1) ? __floats2bfloat162_rn(h1p, h1)
                                    : __floats2bfloat162_rn(h0, h0p);
        uint32_t val = *(uint32_t*)&pk;

        int trow = dir ? (Tn - 1 - t) : t;
        ghs[(uint32_t)trow * 16384 + ghs_ofs] = val;

        if (t + 1 < Tn) {
            const int bb = t & 1;               // barrier for this step
            const int nb = (t + 1) & 1;         // h buffer for next step
            *ownH[nb] = val;                    // own slice: local store
            __syncthreads();
            if (tid < 128) {
                unsigned long long pv = *sndSrc[nb];
#pragma unroll
                for (int p = 0; p < 4; p++)
                    if (p != rank) st_async_b64(aR[nb][p], pv, barH[bb][p]);
            }
            mbar_wait_cluster(bb ? hbar1 : hbar0, (t >> 1) & 1);
            if (tid == 0) mbar_expect(bb ? hbar1 : hbar0, 3072);
            v00 = n00; v01 = n01; v10 = n10; v11 = n11;
        }
    }
}

// ================= Kernel 3: emissions via tensor cores =====================
#define ESTR 264
__global__ __launch_bounds__(128) void k_emit2(const float* __restrict__ b_emit)
{
    extern __shared__ char sm[];
    __nv_bfloat16* As = (__nv_bfloat16*)sm;                     // [64][264]
    __nv_bfloat16* Bs = (__nv_bfloat16*)(sm + 64 * ESTR * 2);   // [32][264]
    float* sbias = (float*)(sm + (64 + 32) * ESTR * 2);         // [32]

    const int tid = threadIdx.x;
    const int bt0 = blockIdx.x * 64;

    {
        int row = tid >> 1, half = tid & 1;
        const uint4* src = (const uint4*)(g_hs_bf + (size_t)(bt0 + row) * 256 + half * 128);
        uint4* dst = (uint4*)(As + row * ESTR + half * 128);
#pragma unroll
        for (int i = 0; i < 16; i++) dst[i] = src[i];
        if (tid < 64) {
            const uint4* ws = (const uint4*)(g_wemit_bf + (size_t)row * 256 + half * 128);
            uint4* wd = (uint4*)(Bs + row * ESTR + half * 128);
#pragma unroll
            for (int i = 0; i < 16; i++) wd[i] = ws[i];
        }
    }
    if (tid < 32) sbias[tid] = (tid < Kn) ? b_emit[tid] : 0.0f;
    __syncthreads();

    const int wid = tid >> 5, lane = tid & 31;
    const int lr = lane & 15, lc = lane >> 4;

    float acc[3][4];
#pragma unroll
    for (int nt = 0; nt < 3; nt++)
#pragma unroll
        for (int q = 0; q < 4; q++) acc[nt][q] = 0.0f;

#pragma unroll
    for (int kk = 0; kk < 16; kk++) {
        uint32_t a0, a1, a2, a3;
        ldm4(a0, a1, a2, a3, smaddr(As + (16 * wid + lr) * ESTR + kk * 16 + lc * 8));
        uint32_t b0[4], b1[4];
        ldm4(b0[0], b0[1], b0[2], b0[3], smaddr(Bs + lr * ESTR + kk * 16 + lc * 8));
        ldm4(b1[0], b1[1], b1[2], b1[3], smaddr(Bs + (16 + lr) * ESTR + kk * 16 + lc * 8));
        mma16816(acc[0], a0, a1, a2, a3, b0[0], b0[2]);   // n 0..7
        mma16816(acc[1], a0, a1, a2, a3, b0[1], b0[3]);   // n 8..15
        mma16816(acc[2], a0, a1, a2, a3, b1[0], b1[2]);   // n 16..23
    }

    const int r = lane >> 2;
#pragma unroll
    for (int nt = 0; nt < 3; nt++) {
#pragma unroll
        for (int q = 0; q < 4; q++) {
            int n = 8 * nt + 2 * (lane & 3) + (q & 1);
            if (n >= Kn) continue;
            int bt = bt0 + 16 * wid + r + ((q >> 1) ? 8 : 0);
            int t = bt >> 7, b = bt & 127;
            g_em[((size_t)b * Tn + t) * Kn + n] = acc[nt][q] + sbias[n];
        }
    }
}

// ================= Kernel 4: CRF fwd/bwd split ===============================
__global__ __launch_bounds__(64) void k_crf3(
    const int* __restrict__ tags,
    const float* __restrict__ start_t,
    const float* __restrict__ end_t,
    const float* __restrict__ trans)
{
    const int b = blockIdx.x;
    const int w = threadIdx.x >> 5;
    const int lane = threadIdx.x & 31;
    const int laneC = (lane < Kn) ? lane : 0;
    const float* em = g_em + (size_t)b * Tn * Kn;
    const int* tg = tags + b * Tn;

    __shared__ float sV[2][Kn];
    __shared__ float sLa[2];
    __shared__ float sNum;

    if (w == 0) {
        // ---- numerator (gold path), lanes strided over t ----
        float s = 0.0f;
        for (int t = lane + 1; t < Tn; t += 32)
            s += trans[tg[t - 1] * Kn + tg[t]] + em[(size_t)t * Kn + tg[t]];
#pragma unroll
        for (int off = 16; off; off >>= 1) s += __shfl_xor_sync(0xffffffffu, s, off);
        s += start_t[tg[0]] + em[tg[0]] + end_t[tg[Tn - 1]];
        if (lane == 0) sNum = s;

        // ---- forward half: alpha over t=1..255 ----
        float tcol[Kn];
#pragma unroll
        for (int i = 0; i < Kn; i++)
            tcol[i] = (lane < Kn) ? __expf(trans[i * Kn + lane]) : 0.0f;
        float A = (lane < Kn) ? __expf(start_t[lane] + em[lane]) : 0.0f;
        float la = 0.0f;
        float eb[4];
#pragma unroll
        for (int q = 0; q < 4; q++) eb[q] = em[(size_t)(1 + q) * Kn + laneC];
        for (int t = 1; t <= 255; t++) {
            float e = eb[(t - 1) & 3];
            if (t + 4 <= 255) eb[(t - 1) & 3] = em[(size_t)(t + 4) * Kn + laneC];
            float sum = 0.0f;
#pragma unroll
            for (int i = 0; i < Kn; i++)
                sum += __shfl_sync(0xffffffffu, A, i) * tcol[i];
            A = sum * __expf(e);
            if ((t & 3) == 3) {
                float m = A;
#pragma unroll
                for (int off = 16; off; off >>= 1)
                    m = fmaxf(m, __shfl_xor_sync(0xffffffffu, m, off));
                la += __logf(m);
                A = __fdividef(A, m);
            }
        }
        if (lane < Kn) sV[0][lane] = A;
        if (lane == 0) sLa[0] = la;
    } else {
        // ---- backward half: beta over t=510..255 (uses em[511..256]) ----
        float trow[Kn];
#pragma unroll
        for (int k = 0; k < Kn; k++)
            trow[k] = (lane < Kn) ? __expf(trans[lane * Kn + k]) : 0.0f;
        float Bv = (lane < Kn) ? __expf(end_t[lane]) : 0.0f;
        float la = 0.0f;
        float eb[4];
#pragma unroll
        for (int q = 0; q < 4; q++) eb[q] = em[(size_t)(511 - q) * Kn + laneC];
        for (int n = 0; n < 256; n++) {
            float e = eb[n & 3];
            if (n + 4 < 256) eb[n & 3] = em[(size_t)(511 - (n + 4)) * Kn + laneC];
            float g = Bv * __expf(e);
            float sum = 0.0f;
#pragma unroll
            for (int k = 0; k < Kn; k++)
                sum += trow[k] * __shfl_sync(0xffffffffu, g, k);
            Bv = sum;
            if ((n & 3) == 3) {
                float m = Bv;
#pragma unroll
                for (int off = 16; off; off >>= 1)
                    m = fmaxf(m, __shfl_xor_sync(0xffffffffu, m, off));
                la += __logf(m);
                Bv = __fdividef(Bv, m);
            }
        }
        if (lane < Kn) sV[1][lane] = Bv;
        if (lane == 0) sLa[1] = la;
    }
    __syncthreads();

    if (w == 0) {
        float x = (lane < Kn) ? sV[0][lane] * sV[1][lane] : 0.0f;
#pragma unroll
        for (int off = 16; off; off >>= 1) x += __shfl_xor_sync(0xffffffffu, x, off);
        float logZ = __logf(x) + sLa[0] + sLa[1];
        if (lane == 0) g_llh[b] = sNum - logZ;
    }
}

// ================= Kernel 5: final mean =====================================
__global__ void k_reduce(float* __restrict__ out)
{
    const int tid = threadIdx.x; // 128
    float v = g_llh[tid];
#pragma unroll
    for (int off = 16; off; off >>= 1) v += __shfl_xor_sync(0xffffffffu, v, off);
    __shared__ float s[4];
    if ((tid & 31) == 0) s[tid >> 5] = v;
    __syncthreads();
    if (tid == 0) out[0] = -(s[0] + s[1] + s[2] + s[3]) / (float)Bn;
}

// ============================================================================
extern "C" void kernel_launch(void* const* d_in, const int* in_sizes, int n_in,
                              void* d_out, int out_size)
{
    const int*   ids     = (const int*)d_in[0];
    const int*   tags    = (const int*)d_in[1];
    // d_in[2] = mask: all-true for this problem; intentionally unused.
    const float* embed   = (const float*)d_in[3];
    const float* w_ih_f  = (const float*)d_in[4];
    const float* w_hh_f  = (const float*)d_in[5];
    const float* b_ih_f  = (const float*)d_in[6];
    const float* b_hh_f  = (const float*)d_in[7];
    const float* w_ih_b  = (const float*)d_in[8];
    const float* w_hh_b  = (const float*)d_in[9];
    const float* b_ih_b  = (const float*)d_in[10];
    const float* b_hh_b  = (const float*)d_in[11];
    const float* w_emit  = (const float*)d_in[12];
    const float* b_emit  = (const float*)d_in[13];
    const float* start_t = (const float*)d_in[14];
    const float* end_t   = (const float*)d_in[15];
    const float* trans   = (const float*)d_in[16];

    const int SMEM_XP2  = 2 * 128 * ASTR * 2 + 512;          // 70,144 B
    const int SMEM_EMIT = (64 + 32) * ESTR * 2 + 128;        // 50,816 B
    cudaFuncSetAttribute(k_xp2,   cudaFuncAttributeMaxDynamicSharedMemorySize, SMEM_XP2);
    cudaFuncSetAttribute(k_emit2, cudaFuncAttributeMaxDynamicSharedMemorySize, SMEM_EMIT);

    k_cvt<<<128, 256>>>(w_ih_f, w_ih_b, b_ih_f, b_hh_f, b_ih_b, b_hh_b, w_emit);
    k_xp2<<<dim3(8, 512), 256, SMEM_XP2>>>(ids, embed);
    k_lstm6<<<64, 256>>>(w_hh_f, w_hh_b);
    k_emit2<<<1024, 128, SMEM_EMIT>>>(b_emit);
    k_crf3<<<128, 64>>>(tags, start_t, end_t, trans);
    k_reduce<<<1, 128>>>((float*)d_out);
}

// round 17
// speedup vs baseline: 1.4286x; 1.4286x over previous
#include <cuda_runtime.h>
#include <cuda_bf16.h>
#include <cstdint>

#define Vn 30000
#define Kn 17
#define En 128
#define Hn 128
#define Bn 128
#define Tn 512
#define G4H 512   // 4*H

// ---------------- scratch (device globals; allocation-free) ----------------
// xp stored bf16, layout [dir][t][rank][b][128] with gate-permuted last dim:
//   c = (widp<<4) | (gp<<3) | (aa<<1) | (gate&1),  j = 32*rank + 4*widp + aa
__device__ __nv_bfloat16 g_xp_bf[(size_t)2 * Tn * 4 * Bn * 128];
__device__ __nv_bfloat16 g_hs_bf[(size_t)Tn * Bn * 2 * Hn];   // [t*B+b][256]
__device__ float g_em[(size_t)Bn * Tn * Kn];                  // [b][t][k]
__device__ float g_llh[Bn];
__device__ __nv_bfloat16 g_embed_bf[(size_t)Vn * En];
__device__ __nv_bfloat16 g_wih_bf[2 * (size_t)G4H * En];      // [dir][g][k]
__device__ __nv_bfloat16 g_wemit_bf[32 * 256];                // rows>=17 zero
__device__ float g_bias[2 * G4H];

__device__ __forceinline__ float tanha(float x) {
    float r; asm("tanh.approx.f32 %0,%1;" : "=f"(r) : "f"(x)); return r;
}
__device__ __forceinline__ float siga(float x) {
    return 0.5f * tanha(0.5f * x) + 0.5f;
}

// ================= Kernel 0: fp32 -> bf16 conversions =======================
__global__ __launch_bounds__(256) void k_cvt(
    const float* __restrict__ embed,
    const float* __restrict__ wf, const float* __restrict__ wb,
    const float* __restrict__ bihf, const float* __restrict__ bhhf,
    const float* __restrict__ bihb, const float* __restrict__ bhhb,
    const float* __restrict__ w_emit)
{
    int i = blockIdx.x * 256 + threadIdx.x;
    if (i < Vn * En / 2) {
        float2 v = ((const float2*)embed)[i];
        ((__nv_bfloat162*)g_embed_bf)[i] = __floats2bfloat162_rn(v.x, v.y);
    }
    if (i < G4H * En / 2) {
        float2 v = ((const float2*)wf)[i];
        ((__nv_bfloat162*)g_wih_bf)[i] = __floats2bfloat162_rn(v.x, v.y);
        float2 u = ((const float2*)wb)[i];
        ((__nv_bfloat162*)g_wih_bf)[G4H * En / 2 + i] = __floats2bfloat162_rn(u.x, u.y);
    }
    if (i < G4H) {
        g_bias[i] = bihf[i] + bhhf[i];
        g_bias[G4H + i] = bihb[i] + bhhb[i];
    }
    if (i < 32 * 128) {   // w_emit padded to 32 rows, bf16
        int row = i >> 7, col2 = i & 127;
        __nv_bfloat162 v;
        if (row < Kn) {
            v = __floats2bfloat162_rn(w_emit[row * 256 + 2 * col2],
                                      w_emit[row * 256 + 2 * col2 + 1]);
        } else {
            v = __floats2bfloat162_rn(0.0f, 0.0f);
        }
        ((__nv_bfloat162*)g_wemit_bf)[i] = v;
    }
}

// ---------------- mma / cluster helpers ----------------
__device__ __forceinline__ uint32_t smaddr(const void* p) {
    return (uint32_t)__cvta_generic_to_shared(p);
}
__device__ __forceinline__ void ldm4(uint32_t& r0, uint32_t& r1, uint32_t& r2, uint32_t& r3, uint32_t a) {
    asm volatile("ldmatrix.sync.aligned.m8n8.x4.shared.b16 {%0,%1,%2,%3},[%4];"
                 : "=r"(r0), "=r"(r1), "=r"(r2), "=r"(r3) : "r"(a));
}
__device__ __forceinline__ void mma16816(float* c, uint32_t a0, uint32_t a1, uint32_t a2, uint32_t a3,
                                         uint32_t b0, uint32_t b1) {
    asm volatile("mma.sync.aligned.m16n8k16.row.col.f32.bf16.bf16.f32 "
                 "{%0,%1,%2,%3},{%4,%5,%6,%7},{%8,%9},{%0,%1,%2,%3};"
                 : "+f"(c[0]), "+f"(c[1]), "+f"(c[2]), "+f"(c[3])
                 : "r"(a0), "r"(a1), "r"(a2), "r"(a3), "r"(b0), "r"(b1));
}
__device__ __forceinline__ uint32_t mapa_u32(uint32_t a, uint32_t rnk) {
    uint32_t d; asm("mapa.shared::cluster.u32 %0,%1,%2;" : "=r"(d) : "r"(a), "r"(rnk));
    return d;
}
__device__ __forceinline__ void mbar_init(uint32_t bar, uint32_t cnt) {
    asm volatile("mbarrier.init.shared.b64 [%0],%1;" :: "r"(bar), "r"(cnt) : "memory");
}
__device__ __forceinline__ void mbar_expect(uint32_t bar, uint32_t tx) {
    asm volatile("mbarrier.arrive.expect_tx.shared.b64 _,[%0],%1;" :: "r"(bar), "r"(tx) : "memory");
}
__device__ __forceinline__ void mbar_wait_cluster(uint32_t bar, uint32_t parity) {
    uint32_t done;
    do {
        asm volatile("{\n\t.reg .pred p;\n\t"
                     "mbarrier.try_wait.parity.acquire.cluster.shared::cta.b64 p,[%1],%2,0x989680;\n\t"
                     "selp.b32 %0,1,0,p;\n\t}"
                     : "=r"(done) : "r"(bar), "r"(parity) : "memory");
    } while (!done);
}
__device__ __forceinline__ void st_async_b64(uint32_t raddr, unsigned long long v, uint32_t rbar) {
    asm volatile("st.async.shared::cluster.mbarrier::complete_tx::bytes.b64 [%0],%1,[%2];"
                 :: "r"(raddr), "l"(v), "r"(rbar) : "memory");
}

#define ASTR 136   // bf16 elems per smem row (128 + 8 pad: conflict-free ldmatrix)

// ================= Kernel 1: input projection, gate-pair fused ==============
// grid (4, 512), 512 threads: x = np2 (dir*2 + gp), y = t. One CTA computes
// the full 256-col gate-pair tile (B rows interleaved n = 2j + (gate&1)), so
// each thread's acc col-pair is (i,f) or (g,o) of one (b,j) -> u32 stores.
__global__ __launch_bounds__(512) void k_xp3(const int* __restrict__ ids)
{
    extern __shared__ char sm[];
    __nv_bfloat16* As = (__nv_bfloat16*)sm;                      // [128][136]
    __nv_bfloat16* Bs = (__nv_bfloat16*)(sm + 128 * ASTR * 2);   // [256][136]
    float* sbias = (float*)(sm + (128 + 256) * ASTR * 2);        // [256]

    const int t = blockIdx.y;
    const int np2 = blockIdx.x;        // 0..3
    const int dir = np2 >> 1;
    const int gp = np2 & 1;            // gate pair: (0,1) or (2,3)
    const int tid = threadIdx.x;

    // ---- load A (embed rows, 4 threads/row) ----
    {
        int r = tid >> 2, qtr = tid & 3;
        int id = ids[r * Tn + t];
        const uint4* src = (const uint4*)(g_embed_bf + (size_t)id * En + qtr * 32);
        uint4* dst = (uint4*)(As + r * ASTR + qtr * 32);
#pragma unroll
        for (int i = 0; i < 4; i++) dst[i] = src[i];
    }
    // ---- load B (w_ih rows, interleaved n = 2j + (gate&1), 2 threads/row) ----
    {
        int n = tid >> 1, half = tid & 1;
        int gate = 2 * gp + (n & 1);
        int j = n >> 1;
        const uint4* wsrc = (const uint4*)(g_wih_bf
            + ((size_t)dir * G4H + gate * 128 + j) * En + half * 64);
        uint4* wdst = (uint4*)(Bs + n * ASTR + half * 64);
#pragma unroll
        for (int i = 0; i < 8; i++) wdst[i] = wsrc[i];
    }
    if (tid < 256)
        sbias[tid] = g_bias[dir * G4H + (2 * gp + (tid & 1)) * 128 + (tid >> 1)];
    __syncthreads();

    const int wid = tid >> 5, lane = tid & 31;
    const int wm = (wid & 3) * 32;     // 4 m-warps
    const int wn = (wid >> 2) * 64;    // 4 n-warps (cover 256)

    float acc[2][8][4];
#pragma unroll
    for (int im = 0; im < 2; im++)
#pragma unroll
        for (int inn = 0; inn < 8; inn++)
#pragma unroll
            for (int q = 0; q < 4; q++) acc[im][inn][q] = 0.0f;

    const int lr = lane & 15, lc = lane >> 4;
#pragma unroll
    for (int kk = 0; kk < 8; kk++) {
        uint32_t a[2][4];
#pragma unroll
        for (int im = 0; im < 2; im++) {
            uint32_t ad = smaddr(As + (wm + im * 16 + lr) * ASTR + kk * 16 + lc * 8);
            ldm4(a[im][0], a[im][1], a[im][2], a[im][3], ad);
        }
        uint32_t b[4][4];
#pragma unroll
        for (int np = 0; np < 4; np++) {
            uint32_t ad = smaddr(Bs + (wn + np * 16 + lr) * ASTR + kk * 16 + lc * 8);
            ldm4(b[np][0], b[np][1], b[np][2], b[np][3], ad);
        }
#pragma unroll
        for (int im = 0; im < 2; im++)
#pragma unroll
            for (int inn = 0; inn < 8; inn++) {
                int np = inn >> 1, hf = inn & 1;
                uint32_t bb0 = hf ? b[np][1] : b[np][0];
                uint32_t bb1 = hf ? b[np][3] : b[np][2];
                mma16816(acc[im][inn], a[im][0], a[im][1], a[im][2], a[im][3], bb0, bb1);
            }
    }

    // ---- epilogue: bias + pack gate-pair bf16x2 + u32 store ----
    const int trow = dir ? (Tn - 1 - t) : t;
    uint32_t* xpo = (uint32_t*)g_xp_bf;
#pragma unroll
    for (int im = 0; im < 2; im++)
#pragma unroll
        for (int inn = 0; inn < 8; inn++) {
            int gl0 = wn + inn * 8 + 2 * (lane & 3);   // even col (gate&1=0)
            float bx = sbias[gl0], by = sbias[gl0 + 1];
            int j = gl0 >> 1;
            int rho = j >> 5, jl = j & 31;
            int widp = jl >> 2, aa = jl & 3;
            int idx = 8 * widp + 4 * gp + aa;          // u32 index within row
            int row0 = wm + im * 16 + (lane >> 2);
            size_t base = (((size_t)(dir * Tn + trow) * 4 + rho) * Bn) * 64;
            __nv_bfloat162 p0 = __floats2bfloat162_rn(acc[im][inn][0] + bx,
                                                      acc[im][inn][1] + by);
            __nv_bfloat162 p1 = __floats2bfloat162_rn(acc[im][inn][2] + bx,
                                                      acc[im][inn][3] + by);
            xpo[base + (size_t)row0 * 64 + idx] = *(uint32_t*)&p0;
            xpo[base + (size_t)(row0 + 8) * 64 + idx] = *(uint32_t*)&p1;
        }
}

// ================= Kernel 2: cluster-4 j-split BiLSTM recurrence ============
// EXACT R13 version (757.9us): monolithic wait, staged st.async exchange,
// two alternating mbarriers (step t uses bars[t&1], parity (t>>1)&1).
__global__ __launch_bounds__(256, 1) __cluster_dims__(4, 1, 1)
void k_lstm6(const float* __restrict__ whhf, const float* __restrict__ whhb)
{
    __shared__ __nv_bfloat16 Wsm[128 * ASTR];
    __shared__ __nv_bfloat16 Hsm[2][16 * ASTR];
    __shared__ __align__(16) uint32_t Sg[256];   // staging [16 rows][16 u32]
    __shared__ __align__(8) unsigned long long hbar_s[2];

    const int cid = blockIdx.x >> 2;
    const int rank = blockIdx.x & 3;
    const int dir = cid >> 3;
    const int b0 = (cid & 7) * 16;
    const float* whh = dir ? whhb : whhf;
    const int tid = threadIdx.x;
    const int wid = tid >> 5, lane = tid & 31;

    // ---- load my 128 permuted W_hh rows as bf16 ----
    {
        int c = tid >> 1, half = tid & 1;
        int gate = (c & 1) + 2 * ((c >> 3) & 1);
        int jl = 4 * (c >> 4) + ((c & 7) >> 1);
        int grow = gate * 128 + 32 * rank + jl;
        const float2* src = (const float2*)(whh + (size_t)grow * Hn + half * 64);
        __nv_bfloat162* dst = (__nv_bfloat162*)(Wsm + c * ASTR + half * 64);
#pragma unroll
        for (int i = 0; i < 32; i++) {
            float2 v = src[i];
            dst[i] = __floats2bfloat162_rn(v.x, v.y);
        }
    }
    for (int i = tid; i < 2 * 16 * ASTR / 2; i += 256) ((uint32_t*)Hsm)[i] = 0u;

    const uint32_t hbar0 = smaddr(&hbar_s[0]);
    const uint32_t hbar1 = smaddr(&hbar_s[1]);
    if (tid == 0) {
        mbar_init(hbar0, 1);
        mbar_init(hbar1, 1);
        mbar_expect(hbar0, 3072);   // phase 0 of barrier 0 (3 peers x 1KB)
        mbar_expect(hbar1, 3072);   // phase 0 of barrier 1
    }
    __syncthreads();
    asm volatile("barrier.cluster.arrive.aligned;" ::: "memory");
    asm volatile("barrier.cluster.wait.aligned;" ::: "memory");

    // ---- hoist W fragments (step-invariant) ----
    const int lr = lane & 15, lc = lane >> 4;
    uint32_t bw[8][4];
#pragma unroll
    for (int kk = 0; kk < 8; kk++)
        ldm4(bw[kk][0], bw[kk][1], bw[kk][2], bw[kk][3],
             smaddr(Wsm + (16 * wid + lr) * ASTR + kk * 16 + lc * 8));

    // ---- thread coords & precomputed addresses ----
    const int a = lane & 3, r = lane >> 2;
    const int cb = 16 * wid + 2 * a;
    const int j = 32 * rank + 4 * wid + a;
    const int destrow = (a & 1) ? (r + 8) : r;
    const int destcol = (a & 1) ? (j - 1) : j;   // even
    uint32_t* ownH[2];
    ownH[0] = (uint32_t*)&Hsm[0][destrow * ASTR + destcol];
    ownH[1] = (uint32_t*)&Hsm[1][destrow * ASTR + destcol];
    const int sgIdx = destrow * 16 + ((destcol >> 1) & 15);

    // sender thread (tid<128) remote addresses: row=tid>>3, pair=tid&7
    const int srow = tid >> 3, spr = tid & 7;
    uint32_t aR[2][4], barH[2][4];
#pragma unroll
    for (int buf = 0; buf < 2; buf++) {
        uint32_t la = smaddr(&Hsm[buf][srow * ASTR + 32 * rank + 4 * spr]);
#pragma unroll
        for (int p = 0; p < 4; p++) aR[buf][p] = mapa_u32(la, p);
    }
#pragma unroll
    for (int p = 0; p < 4; p++) {
        barH[0][p] = mapa_u32(hbar0, p);
        barH[1][p] = mapa_u32(hbar1, p);
    }

    const uint32_t* xb = (const uint32_t*)g_xp_bf
        + ((size_t)dir * Tn * 4 + rank) * Bn * 64 + (size_t)(b0 + r) * 64 + (cb >> 1);
    const size_t tstep = 4 * (size_t)Bn * 64;   // u32 per t

    const uint32_t ghs_ofs = (uint32_t)(((b0 + destrow) * 256 + dir * 128 + destcol) >> 1);
    uint32_t* ghs = (uint32_t*)g_hs_bf;

    uint32_t v00 = xb[0], v01 = xb[4], v10 = xb[512], v11 = xb[516];
    float creg0 = 0.0f, creg1 = 0.0f;

    for (int t = 0; t < Tn; t++) {
        uint32_t n00, n01, n10, n11;
        if (t + 1 < Tn) {
            const uint32_t* p = xb + (size_t)(t + 1) * tstep;
            n00 = p[0]; n01 = p[4]; n10 = p[512]; n11 = p[516];
        }
        // acc init from permuted xp: acc0={i,f}(r),(r+8); acc1={g,o}(r),(r+8)
        float acc0[4], acc1[4];
        {
            __nv_bfloat162 u;
            u = *(__nv_bfloat162*)&v00; acc0[0] = __bfloat162float(u.x); acc0[1] = __bfloat162float(u.y);
            u = *(__nv_bfloat162*)&v10; acc0[2] = __bfloat162float(u.x); acc0[3] = __bfloat162float(u.y);
            u = *(__nv_bfloat162*)&v01; acc1[0] = __bfloat162float(u.x); acc1[1] = __bfloat162float(u.y);
            u = *(__nv_bfloat162*)&v11; acc1[2] = __bfloat162float(u.x); acc1[3] = __bfloat162float(u.y);
        }
        // GEMM from current h buffer
        const __nv_bfloat16* hb = Hsm[t & 1];
#pragma unroll
        for (int kk = 0; kk < 8; kk++) {
            uint32_t a0, a1, a2, a3;
            ldm4(a0, a1, a2, a3, smaddr(hb + lr * ASTR + kk * 16 + lc * 8));
            mma16816(acc0, a0, a1, a2, a3, bw[kk][0], bw[kk][2]);
            mma16816(acc1, a0, a1, a2, a3, bw[kk][1], bw[kk][3]);
        }
        // pointwise in registers: (i,f,g,o) at (b=r / r+8, j)
        creg0 = siga(acc0[1]) * creg0 + siga(acc0[0]) * tanha(acc1[0]);
        float h0 = siga(acc1[1]) * tanha(creg0);
        creg1 = siga(acc0[3]) * creg1 + siga(acc0[2]) * tanha(acc1[2]);
        float h1 = siga(acc1[3]) * tanha(creg1);

        float h0p = __shfl_xor_sync(0xffffffffu, h0, 1);
        float h1p = __shfl_xor_sync(0xffffffffu, h1, 1);
        __nv_bfloat162 pk = (a & 1) ? __floats2bfloat162_rn(h1p, h1)
                                    : __floats2bfloat162_rn(h0, h0p);
        uint32_t val = *(uint32_t*)&pk;

        int trow = dir ? (Tn - 1 - t) : t;
        ghs[(uint32_t)trow * 16384 + ghs_ofs] = val;

        if (t + 1 < Tn) {
            const int bb = t & 1;               // barrier for this step
            const int nb = (t + 1) & 1;         // h buffer for next step
            // own slice: local store; remote slices: staged coalesced send
            *ownH[nb] = val;
            Sg[sgIdx] = val;
            __syncthreads();
            if (tid < 128) {
                uint2 v2 = ((const uint2*)Sg)[tid];
                unsigned long long pv = ((unsigned long long)v2.y << 32) | v2.x;
#pragma unroll
                for (int p = 0; p < 4; p++)
                    if (p != rank) st_async_b64(aR[nb][p], pv, barH[bb][p]);
            }
            mbar_wait_cluster(bb ? hbar1 : hbar0, (t >> 1) & 1);
            if (tid == 0) mbar_expect(bb ? hbar1 : hbar0, 3072);
            v00 = n00; v01 = n01; v10 = n10; v11 = n11;
        }
    }
}

// ================= Kernel 3: emissions via tensor cores =====================
#define ESTR 264
__global__ __launch_bounds__(128) void k_emit2(const float* __restrict__ b_emit)
{
    extern __shared__ char sm[];
    __nv_bfloat16* As = (__nv_bfloat16*)sm;                     // [64][264]
    __nv_bfloat16* Bs = (__nv_bfloat16*)(sm + 64 * ESTR * 2);   // [32][264]
    float* sbias = (float*)(sm + (64 + 32) * ESTR * 2);         // [32]

    const int tid = threadIdx.x;
    const int bt0 = blockIdx.x * 64;

    {
        int row = tid >> 1, half = tid & 1;
        const uint4* src = (const uint4*)(g_hs_bf + (size_t)(bt0 + row) * 256 + half * 128);
        uint4* dst = (uint4*)(As + row * ESTR + half * 128);
#pragma unroll
        for (int i = 0; i < 16; i++) dst[i] = src[i];
        if (tid < 64) {
            const uint4* ws = (const uint4*)(g_wemit_bf + (size_t)row * 256 + half * 128);
            uint4* wd = (uint4*)(Bs + row * ESTR + half * 128);
#pragma unroll
            for (int i = 0; i < 16; i++) wd[i] = ws[i];
        }
    }
    if (tid < 32) sbias[tid] = (tid < Kn) ? b_emit[tid] : 0.0f;
    __syncthreads();

    const int wid = tid >> 5, lane = tid & 31;
    const int lr = lane & 15, lc = lane >> 4;

    float acc[3][4];
#pragma unroll
    for (int nt = 0; nt < 3; nt++)
#pragma unroll
        for (int q = 0; q < 4; q++) acc[nt][q] = 0.0f;

#pragma unroll
    for (int kk = 0; kk < 16; kk++) {
        uint32_t a0, a1, a2, a3;
        ldm4(a0, a1, a2, a3, smaddr(As + (16 * wid + lr) * ESTR + kk * 16 + lc * 8));
        uint32_t b0[4], b1[4];
        ldm4(b0[0], b0[1], b0[2], b0[3], smaddr(Bs + lr * ESTR + kk * 16 + lc * 8));
        ldm4(b1[0], b1[1], b1[2], b1[3], smaddr(Bs + (16 + lr) * ESTR + kk * 16 + lc * 8));
        mma16816(acc[0], a0, a1, a2, a3, b0[0], b0[2]);   // n 0..7
        mma16816(acc[1], a0, a1, a2, a3, b0[1], b0[3]);   // n 8..15
        mma16816(acc[2], a0, a1, a2, a3, b1[0], b1[2]);   // n 16..23
    }

    const int r = lane >> 2;
#pragma unroll
    for (int nt = 0; nt < 3; nt++) {
#pragma unroll
        for (int q = 0; q < 4; q++) {
            int n = 8 * nt + 2 * (lane & 3) + (q & 1);
            if (n >= Kn) continue;
            int bt = bt0 + 16 * wid + r + ((q >> 1) ? 8 : 0);
            int t = bt >> 7, b = bt & 127;
            g_em[((size_t)b * Tn + t) * Kn + n] = acc[nt][q] + sbias[n];
        }
    }
}

// ================= Kernel 4: CRF forward/backward split, 1 batch/block ======
__global__ __launch_bounds__(64) void k_crf3(
    const int* __restrict__ tags,
    const float* __restrict__ start_t,
    const float* __restrict__ end_t,
    const float* __restrict__ trans)
{
    const int b = blockIdx.x;
    const int w = threadIdx.x >> 5;
    const int lane = threadIdx.x & 31;
    const int laneC = (lane < Kn) ? lane : 0;
    const float* em = g_em + (size_t)b * Tn * Kn;
    const int* tg = tags + b * Tn;

    __shared__ float sV[2][Kn];
    __shared__ float sLa[2];
    __shared__ float sNum;

    if (w == 0) {
        // ---- numerator (gold path), lanes strided over t ----
        float s = 0.0f;
        for (int t = lane + 1; t < Tn; t += 32)
            s += trans[tg[t - 1] * Kn + tg[t]] + em[(size_t)t * Kn + tg[t]];
#pragma unroll
        for (int off = 16; off; off >>= 1) s += __shfl_xor_sync(0xffffffffu, s, off);
        s += start_t[tg[0]] + em[tg[0]] + end_t[tg[Tn - 1]];
        if (lane == 0) sNum = s;

        // ---- forward half: alpha over t=1..255 ----
        float tcol[Kn];
#pragma unroll
        for (int i = 0; i < Kn; i++)
            tcol[i] = (lane < Kn) ? __expf(trans[i * Kn + lane]) : 0.0f;
        float A = (lane < Kn) ? __expf(start_t[lane] + em[lane]) : 0.0f;
        float la = 0.0f;
        float ec = em[Kn + laneC];
        for (int t = 1; t <= 255; t++) {
            float en = (t < 255) ? em[(size_t)(t + 1) * Kn + laneC] : 0.0f;
            float sum = 0.0f;
#pragma unroll
            for (int i = 0; i < Kn; i++)
                sum += __shfl_sync(0xffffffffu, A, i) * tcol[i];
            A = sum * __expf(ec);
            if ((t & 3) == 3) {
                float m = A;
#pragma unroll
                for (int off = 16; off; off >>= 1)
                    m = fmaxf(m, __shfl_xor_sync(0xffffffffu, m, off));
                la += __logf(m);
                A = __fdividef(A, m);
            }
            ec = en;
        }
        if (lane < Kn) sV[0][lane] = A;
        if (lane == 0) sLa[0] = la;
    } else {
        // ---- backward half: beta over t=510..255 ----
        float trow[Kn];
#pragma unroll
        for (int k = 0; k < Kn; k++)
            trow[k] = (lane < Kn) ? __expf(trans[lane * Kn + k]) : 0.0f;
        float Bv = (lane < Kn) ? __expf(end_t[lane]) : 0.0f;
        float la = 0.0f;
        float ep = em[(size_t)511 * Kn + laneC];   // e_{t+1} for t=510
        int rc = 0;
        for (int t = 510; t >= 255; t--) {
            float en = (t > 255) ? em[(size_t)t * Kn + laneC] : 0.0f;
            float g = Bv * __expf(ep);
            float sum = 0.0f;
#pragma unroll
            for (int k = 0; k < Kn; k++)
                sum += trow[k] * __shfl_sync(0xffffffffu, g, k);
            Bv = sum;
            if ((++rc & 3) == 0) {
                float m = Bv;
#pragma unroll
                for (int off = 16; off; off >>= 1)
                    m = fmaxf(m, __shfl_xor_sync(0xffffffffu, m, off));
                la += __logf(m);
                Bv = __fdividef(Bv, m);
            }
            ep = en;
        }
        if (lane < Kn) sV[1][lane] = Bv;
        if (lane == 0) sLa[1] = la;
    }
    __syncthreads();

    if (w == 0) {
        float x = (lane < Kn) ? sV[0][lane] * sV[1][lane] : 0.0f;
#pragma unroll
        for (int off = 16; off; off >>= 1) x += __shfl_xor_sync(0xffffffffu, x, off);
        float logZ = __logf(x) + sLa[0] + sLa[1];
        if (lane == 0) g_llh[b] = sNum - logZ;
    }
}

// ================= Kernel 5: final mean =====================================
__global__ void k_reduce(float* __restrict__ out)
{
    const int tid = threadIdx.x; // 128
    float v = g_llh[tid];
#pragma unroll
    for (int off = 16; off; off >>= 1) v += __shfl_xor_sync(0xffffffffu, v, off);
    __shared__ float s[4];
    if ((tid & 31) == 0) s[tid >> 5] = v;
    __syncthreads();
    if (tid == 0) out[0] = -(s[0] + s[1] + s[2] + s[3]) / (float)Bn;
}

// ============================================================================
extern "C" void kernel_launch(void* const* d_in, const int* in_sizes, int n_in,
                              void* d_out, int out_size)
{
    const int*   ids     = (const int*)d_in[0];
    const int*   tags    = (const int*)d_in[1];
    // d_in[2] = mask: all-true for this problem; intentionally unused.
    const float* embed   = (const float*)d_in[3];
    const float* w_ih_f  = (const float*)d_in[4];
    const float* w_hh_f  = (const float*)d_in[5];
    const float* b_ih_f  = (const float*)d_in[6];
    const float* b_hh_f  = (const float*)d_in[7];
    const float* w_ih_b  = (const float*)d_in[8];
    const float* w_hh_b  = (const float*)d_in[9];
    const float* b_ih_b  = (const float*)d_in[10];
    const float* b_hh_b  = (const float*)d_in[11];
    const float* w_emit  = (const float*)d_in[12];
    const float* b_emit  = (const float*)d_in[13];
    const float* start_t = (const float*)d_in[14];
    const float* end_t   = (const float*)d_in[15];
    const float* trans   = (const float*)d_in[16];

    const int SMEM_XP3  = (128 + 256) * ASTR * 2 + 1024;     // 105,472 B
    const int SMEM_EMIT = (64 + 32) * ESTR * 2 + 128;        // 50,816 B
    cudaFuncSetAttribute(k_xp3,   cudaFuncAttributeMaxDynamicSharedMemorySize, SMEM_XP3);
    cudaFuncSetAttribute(k_emit2, cudaFuncAttributeMaxDynamicSharedMemorySize, SMEM_EMIT);

    k_cvt<<<Vn * En / 2 / 256, 256>>>(embed, w_ih_f, w_ih_b,
                                      b_ih_f, b_hh_f, b_ih_b, b_hh_b, w_emit);
    k_xp3<<<dim3(4, 512), 512, SMEM_XP3>>>(ids);
    k_lstm6<<<64, 256>>>(w_hh_f, w_hh_b);
    k_emit2<<<1024, 128, SMEM_EMIT>>>(b_emit);
    k_crf3<<<128, 64>>>(tags, start_t, end_t, trans);
    k_reduce<<<1, 128>>>((float*)d_out);
}